// round 1
// baseline (speedup 1.0000x reference)
#include <cuda_runtime.h>
#include <math.h>

// Problem constants
#define Bn 2048
#define Cn 50000
#define Dn 128
#define Sf 20.0f
#define EPSf 1e-7f
// cos(0.1), sin(0.1)
#define COS_M 0.9950041652780258f
#define SIN_M 0.09983341664682815f

// Scratch (no allocations allowed)
__device__ float g_e[Bn * Dn];        // normalized embeddings  (1 MB)
__device__ float g_Wn[Cn * Dn];       // normalized weights     (25.6 MB)
__device__ float g_loss[Bn];          // per-row loss

// ---------------------------------------------------------------------------
// Row L2-normalize: one warp per row of 128 floats (float4 per lane).
// which=0 -> g_e, which=1 -> g_Wn
// ---------------------------------------------------------------------------
__global__ __launch_bounds__(256) void norm_rows(const float* __restrict__ in,
                                                 int nrows, int which) {
    int warp = (blockIdx.x * blockDim.x + threadIdx.x) >> 5;
    int lane = threadIdx.x & 31;
    if (warp >= nrows) return;
    const float4* ip = (const float4*)(in + (size_t)warp * Dn);
    float4 v = ip[lane];
    float ss = v.x * v.x + v.y * v.y + v.z * v.z + v.w * v.w;
#pragma unroll
    for (int o = 16; o; o >>= 1) ss += __shfl_xor_sync(0xffffffffu, ss, o);
    float scale = 1.0f / fmaxf(sqrtf(ss), 1e-12f);
    float* outb = which ? g_Wn : g_e;
    float4* op = (float4*)(outb + (size_t)warp * Dn);
    op[lane] = make_float4(v.x * scale, v.y * scale, v.z * scale, v.w * scale);
}

// ---------------------------------------------------------------------------
// GEMM: wf[r][c] = sum_k g_e[r][k]*g_Wn[c][k] + bias[c]
// 64x64 tile, 256 threads, 4x4 micro-tile, BK=16.
// ---------------------------------------------------------------------------
__global__ __launch_bounds__(256) void gemm_wf(const float* __restrict__ bias,
                                               float* __restrict__ wf) {
    __shared__ float As[16][64];
    __shared__ float Bs[16][64];
    int row0 = blockIdx.y * 64;
    int col0 = blockIdx.x * 64;
    int t = threadIdx.x;
    int tr = t >> 4;       // 0..15
    int tc = t & 15;       // 0..15
    int lr = t >> 2;       // 0..63 (row/col within tile for loads)
    int lk = (t & 3) * 4;  // 0,4,8,12 (k offset for loads)

    float acc[4][4] = {};

    for (int kt = 0; kt < Dn; kt += 16) {
        // load A tile (rows always in-bounds: Bn % 64 == 0)
        float4 av = *(const float4*)&g_e[(size_t)(row0 + lr) * Dn + kt + lk];
        As[lk + 0][lr] = av.x; As[lk + 1][lr] = av.y;
        As[lk + 2][lr] = av.z; As[lk + 3][lr] = av.w;
        // load B tile (guard tail columns)
        int c = col0 + lr;
        float4 bv = make_float4(0.f, 0.f, 0.f, 0.f);
        if (c < Cn) bv = *(const float4*)&g_Wn[(size_t)c * Dn + kt + lk];
        Bs[lk + 0][lr] = bv.x; Bs[lk + 1][lr] = bv.y;
        Bs[lk + 2][lr] = bv.z; Bs[lk + 3][lr] = bv.w;
        __syncthreads();
#pragma unroll
        for (int k = 0; k < 16; k++) {
            float4 a4 = *(const float4*)&As[k][tr * 4];
            float4 b4 = *(const float4*)&Bs[k][tc * 4];
            acc[0][0] += a4.x * b4.x; acc[0][1] += a4.x * b4.y;
            acc[0][2] += a4.x * b4.z; acc[0][3] += a4.x * b4.w;
            acc[1][0] += a4.y * b4.x; acc[1][1] += a4.y * b4.y;
            acc[1][2] += a4.y * b4.z; acc[1][3] += a4.y * b4.w;
            acc[2][0] += a4.z * b4.x; acc[2][1] += a4.z * b4.y;
            acc[2][2] += a4.z * b4.z; acc[2][3] += a4.z * b4.w;
            acc[3][0] += a4.w * b4.x; acc[3][1] += a4.w * b4.y;
            acc[3][2] += a4.w * b4.z; acc[3][3] += a4.w * b4.w;
        }
        __syncthreads();
    }

    int col = col0 + tc * 4;
    if (col < Cn) {  // Cn % 4 == 0, so col<Cn implies col+3<Cn
        float4 bb = *(const float4*)&bias[col];
#pragma unroll
        for (int i = 0; i < 4; i++) {
            int r = row0 + tr * 4 + i;
            float4 o = make_float4(acc[i][0] + bb.x, acc[i][1] + bb.y,
                                   acc[i][2] + bb.z, acc[i][3] + bb.w);
            *(float4*)&wf[(size_t)r * Cn + col] = o;
        }
    }
}

// ---------------------------------------------------------------------------
// Block reductions (deterministic tree)
// ---------------------------------------------------------------------------
__device__ __forceinline__ float block_max(float v, float* red, int t) {
    red[t] = v; __syncthreads();
#pragma unroll
    for (int s = 128; s; s >>= 1) {
        if (t < s) red[t] = fmaxf(red[t], red[t + s]);
        __syncthreads();
    }
    float r = red[0]; __syncthreads();
    return r;
}
__device__ __forceinline__ float block_sum(float v, float* red, int t) {
    red[t] = v; __syncthreads();
#pragma unroll
    for (int s = 128; s; s >>= 1) {
        if (t < s) red[t] += red[t + s];
        __syncthreads();
    }
    float r = red[0]; __syncthreads();
    return r;
}

// ---------------------------------------------------------------------------
// Per-row: softmax stats + ArcFace loss + in-place prediction write.
// One CTA (256 threads) per row; three passes over the 200 KB row (L2-hot
// after the first pass).
// ---------------------------------------------------------------------------
__global__ __launch_bounds__(256) void rowstats(float* __restrict__ wf,
                                                const int* __restrict__ labels) {
    int row = blockIdx.x;
    float* ptr = wf + (size_t)row * Cn;
    const float4* p4 = (const float4*)ptr;
    float4* pw = (float4*)ptr;
    int label = labels[row];
    int t = threadIdx.x;

    __shared__ float red[256];
    __shared__ float sh_wl;

    // ---- pass 1: max over row (m1) and max excluding label (m2) ----
    float m1 = -1e30f, m2 = -1e30f;
    for (int i = t; i < Cn / 4; i += 256) {
        float4 v = p4[i];
        m1 = fmaxf(m1, fmaxf(fmaxf(v.x, v.y), fmaxf(v.z, v.w)));
        float a = v.x, b = v.y, c = v.z, d = v.w;
        int base = i * 4;
        if ((unsigned)(label - base) < 4u) {
            int off = label - base;
            float wl = (off == 0) ? a : (off == 1) ? b : (off == 2) ? c : d;
            sh_wl = wl;
            if (off == 0) a = -1e30f; else if (off == 1) b = -1e30f;
            else if (off == 2) c = -1e30f; else d = -1e30f;
        }
        m2 = fmaxf(m2, fmaxf(fmaxf(a, b), fmaxf(c, d)));
    }
    float m1r = block_max(m1, red, t);   // syncthreads inside makes sh_wl visible
    float m2r = block_max(m2, red, t);

    float wl = sh_wl;
    float cc = fminf(fmaxf(wl, -1.0f + EPSf), 1.0f - EPSf);
    float cosm = cc * COS_M - sqrtf(fmaxf(1.0f - cc * cc, 0.0f)) * SIN_M;
    float L = Sf * fmaxf(m2r, cosm);   // max of margined logits row

    // ---- pass 2: sums ----
    float sp = 0.0f;   // sum exp(wf - m1)          (prediction softmax)
    float sl = 0.0f;   // sum_{j != label} exp(S*wf_j - L)
    for (int i = t; i < Cn / 4; i += 256) {
        float4 v = p4[i];
        sp += expf(v.x - m1r) + expf(v.y - m1r) + expf(v.z - m1r) + expf(v.w - m1r);
        float e0 = expf(Sf * v.x - L);
        float e1 = expf(Sf * v.y - L);
        float e2 = expf(Sf * v.z - L);
        float e3 = expf(Sf * v.w - L);
        int base = i * 4;
        if ((unsigned)(label - base) < 4u) {
            int off = label - base;
            if (off == 0) e0 = 0.f; else if (off == 1) e1 = 0.f;
            else if (off == 2) e2 = 0.f; else e3 = 0.f;
        }
        sl += e0 + e1 + e2 + e3;
    }
    float spr = block_sum(sp, red, t);
    float slr = block_sum(sl, red, t);

    if (t == 0) {
        float slt = slr + expf(Sf * cosm - L);
        g_loss[row] = -(Sf * cosm - L - logf(slt));
    }

    // ---- pass 3: prediction in place ----
    float inv = 1.0f / spr;
    for (int i = t; i < Cn / 4; i += 256) {
        float4 v = p4[i];
        v.x = expf(v.x - m1r) * inv;
        v.y = expf(v.y - m1r) * inv;
        v.z = expf(v.z - m1r) * inv;
        v.w = expf(v.w - m1r) * inv;
        pw[i] = v;
    }
}

// ---------------------------------------------------------------------------
// Deterministic loss mean reduction -> out[B*C]
// ---------------------------------------------------------------------------
__global__ __launch_bounds__(256) void loss_reduce(float* __restrict__ out) {
    __shared__ float red[256];
    int t = threadIdx.x;
    float s = 0.0f;
    for (int i = t; i < Bn; i += 256) s += g_loss[i];
    red[t] = s; __syncthreads();
#pragma unroll
    for (int st = 128; st; st >>= 1) {
        if (t < st) red[t] += red[t + st];
        __syncthreads();
    }
    if (t == 0) out[(size_t)Bn * Cn] = red[0] / (float)Bn;
}

// ---------------------------------------------------------------------------
extern "C" void kernel_launch(void* const* d_in, const int* in_sizes, int n_in,
                              void* d_out, int out_size) {
    const float* x      = (const float*)d_in[0];   // [B, D]
    const float* W      = (const float*)d_in[1];   // [C, D]
    const float* bias   = (const float*)d_in[2];   // [C]
    const int*   labels = (const int*)d_in[3];     // [B]
    float* out = (float*)d_out;                    // [B*C] prediction + [1] loss

    // normalize (warp per row; 8 rows per 256-thread block)
    norm_rows<<<Bn / 8, 256>>>(x, Bn, 0);
    norm_rows<<<(Cn + 7) / 8, 256>>>(W, Cn, 1);

    // wf -> out[0..B*C)
    dim3 gg((Cn + 63) / 64, Bn / 64);
    gemm_wf<<<gg, 256>>>(bias, out);

    // per-row softmax / margin / loss, prediction written in place
    rowstats<<<Bn, 256>>>(out, labels);

    // scalar loss
    loss_reduce<<<1, 256>>>(out);
}

// round 5
// speedup vs baseline: 2.2080x; 2.2080x over previous
#include <cuda_runtime.h>
#include <cuda_bf16.h>
#include <math.h>
#include <stdint.h>

// Problem constants
#define Bn 2048
#define Cn 50000
#define Dn 128
#define CPAD 50048            // Cn padded to multiple of 64
#define NCT (CPAD / 64)       // 782 column tiles
#define NRT (Bn / 128)        // 16 row tiles
#define Sf 20.0f
#define EPSf 1e-7f
#define COS_M 0.9950041652780258f
#define SIN_M 0.09983341664682815f

// Plain row-major bf16 scratch: [row][128]
__device__ __align__(16) __nv_bfloat16 g_Ah[(size_t)Bn * Dn];
__device__ __align__(16) __nv_bfloat16 g_Al[(size_t)Bn * Dn];
__device__ __align__(16) __nv_bfloat16 g_Bh[(size_t)CPAD * Dn];
__device__ __align__(16) __nv_bfloat16 g_Bl[(size_t)CPAD * Dn];
__device__ float g_loss[Bn];

// ---------------------------------------------------------------------------
__device__ __forceinline__ void mma16816(float* c, const uint32_t* a,
                                         uint32_t b0, uint32_t b1) {
    asm volatile(
        "mma.sync.aligned.m16n8k16.row.col.f32.bf16.bf16.f32 "
        "{%0,%1,%2,%3}, {%4,%5,%6,%7}, {%8,%9}, {%0,%1,%2,%3};"
        : "+f"(c[0]), "+f"(c[1]), "+f"(c[2]), "+f"(c[3])
        : "r"(a[0]), "r"(a[1]), "r"(a[2]), "r"(a[3]), "r"(b0), "r"(b1));
}

// ---------------------------------------------------------------------------
// Normalize + split fp32 -> bf16 hi/lo, plain row-major. One warp per row.
// Output arrays bound INSIDE device code (device symbols are not valid as
// host-side kernel args -- that was the r2-r4 bug).
// ---------------------------------------------------------------------------
__global__ __launch_bounds__(256) void norm_split(const float* __restrict__ in,
                                                  int nrows, int npad,
                                                  int which) {
    int warp = (blockIdx.x * blockDim.x + threadIdx.x) >> 5;
    int lane = threadIdx.x & 31;
    if (warp >= npad) return;
    float4 v = make_float4(0.f, 0.f, 0.f, 0.f);
    if (warp < nrows) v = ((const float4*)(in + (size_t)warp * Dn))[lane];
    float ss = v.x * v.x + v.y * v.y + v.z * v.z + v.w * v.w;
#pragma unroll
    for (int o = 16; o; o >>= 1) ss += __shfl_xor_sync(0xffffffffu, ss, o);
    float sc = 1.0f / fmaxf(sqrtf(ss), 1e-12f);
    if (warp >= nrows) sc = 0.0f;
    v.x *= sc; v.y *= sc; v.z *= sc; v.w *= sc;

    __nv_bfloat162 h01 = __floats2bfloat162_rn(v.x, v.y);
    __nv_bfloat162 h23 = __floats2bfloat162_rn(v.z, v.w);
    __nv_bfloat162 l01 = __floats2bfloat162_rn(v.x - __bfloat162float(h01.x),
                                               v.y - __bfloat162float(h01.y));
    __nv_bfloat162 l23 = __floats2bfloat162_rn(v.z - __bfloat162float(h23.x),
                                               v.w - __bfloat162float(h23.y));

    __nv_bfloat16* hi = which ? g_Bh : g_Ah;
    __nv_bfloat16* lo = which ? g_Bl : g_Al;
    size_t idx = (size_t)warp * Dn + 4 * lane;
    uint2 hv, lv;
    hv.x = *(uint32_t*)&h01; hv.y = *(uint32_t*)&h23;
    lv.x = *(uint32_t*)&l01; lv.y = *(uint32_t*)&l23;
    *(uint2*)(hi + idx) = hv;
    *(uint2*)(lo + idx) = lv;
}

// ---------------------------------------------------------------------------
// mma.sync bf16 GEMM, explicit per-lane fragment LDS (no ldmatrix, no swizzle).
// CTA tile 128x64, 256 threads (8 warps of 32x32), full K=128 in SMEM.
// SMEM as uint32 words, row stride 68 (64 data + 4 pad):
//   sAh[128*68] sAl[128*68] sBh[64*68] sBl[64*68]  -> 104448 bytes
// ---------------------------------------------------------------------------
#define RW 68                          // words per smem row
#define WO_AH 0
#define WO_AL (128 * RW)
#define WO_BH (2 * 128 * RW)
#define WO_BL (2 * 128 * RW + 64 * RW)
#define SM_WORDS (2 * 128 * RW + 2 * 64 * RW)
#define SM_TOTAL (SM_WORDS * 4)

__global__ __launch_bounds__(256) void gemm_mma(const float* __restrict__ bias,
                                                float* __restrict__ wf) {
    extern __shared__ uint32_t sw[];
    int t = threadIdx.x;
    int w = t >> 5, lane = t & 31;
    int row0 = blockIdx.x * 128;       // row tile fastest: B tile reused 16x
    int col0 = blockIdx.y * 64;

    // ---- copies: global row (16 uint4) -> smem row (17 uint4, last = pad) ----
    {
        uint4* s4 = (uint4*)sw;
        const uint4* gah = (const uint4*)(g_Ah + (size_t)row0 * Dn);
        const uint4* gal = (const uint4*)(g_Al + (size_t)row0 * Dn);
#pragma unroll
        for (int i = 0; i < 8; i++) {              // 2048 uint4 per A matrix
            int idx = t + i * 256;
            int r = idx >> 4, q = idx & 15;
            s4[(WO_AH / 4) + r * 17 + q] = gah[r * 16 + q];
            s4[(WO_AL / 4) + r * 17 + q] = gal[r * 16 + q];
        }
        const uint4* gbh = (const uint4*)(g_Bh + (size_t)col0 * Dn);
        const uint4* gbl = (const uint4*)(g_Bl + (size_t)col0 * Dn);
#pragma unroll
        for (int i = 0; i < 4; i++) {              // 1024 uint4 per B matrix
            int idx = t + i * 256;
            int r = idx >> 4, q = idx & 15;
            s4[(WO_BH / 4) + r * 17 + q] = gbh[r * 16 + q];
            s4[(WO_BL / 4) + r * 17 + q] = gbl[r * 16 + q];
        }
    }
    __syncthreads();

    int wr = w & 3;                    // row group: 4 x 32 rows
    int wc = w >> 2;                   // col group: 2 x 32 cols
    int rq = lane >> 2;                // groupID
    int tig = lane & 3;                // threadID_in_group

    float acc[2][4][4];
#pragma unroll
    for (int mt = 0; mt < 2; mt++)
#pragma unroll
        for (int nt = 0; nt < 4; nt++)
#pragma unroll
            for (int i = 0; i < 4; i++) acc[mt][nt][i] = 0.f;

    for (int ks = 0; ks < 8; ks++) {
        int kw = ks * 8;               // k16 = 8 words
        uint32_t ah[2][4], al[2][4];
#pragma unroll
        for (int mt = 0; mt < 2; mt++) {
            int r0 = (wr * 32 + mt * 16 + rq) * RW + kw + tig;
            int r1 = r0 + 8 * RW;
            ah[mt][0] = sw[WO_AH + r0];     // (row=g,   k=kb+2*tig)
            ah[mt][1] = sw[WO_AH + r1];     // (row=g+8, k low)
            ah[mt][2] = sw[WO_AH + r0 + 4]; // (row=g,   k high)
            ah[mt][3] = sw[WO_AH + r1 + 4];
            al[mt][0] = sw[WO_AL + r0];
            al[mt][1] = sw[WO_AL + r1];
            al[mt][2] = sw[WO_AL + r0 + 4];
            al[mt][3] = sw[WO_AL + r1 + 4];
        }
#pragma unroll
        for (int nt = 0; nt < 4; nt++) {
            int rb = (wc * 32 + nt * 8 + rq) * RW + kw + tig;
            uint32_t bh0 = sw[WO_BH + rb];      // (n=g, k low)
            uint32_t bh1 = sw[WO_BH + rb + 4];  // (n=g, k high)
            uint32_t bl0 = sw[WO_BL + rb];
            uint32_t bl1 = sw[WO_BL + rb + 4];
#pragma unroll
            for (int mt = 0; mt < 2; mt++) {
                mma16816(acc[mt][nt], ah[mt], bh0, bh1);  // Ah*Bh
                mma16816(acc[mt][nt], ah[mt], bl0, bl1);  // Ah*Bl
                mma16816(acc[mt][nt], al[mt], bh0, bh1);  // Al*Bh
            }
        }
    }

    // ---- epilogue: bias + direct float2 stores ----
    int cq = tig * 2;
#pragma unroll
    for (int nt = 0; nt < 4; nt++) {
        int col = col0 + wc * 32 + nt * 8 + cq;
        if (col >= Cn) continue;
        float2 b2 = *(const float2*)&bias[col];
#pragma unroll
        for (int mt = 0; mt < 2; mt++) {
            int r = row0 + wr * 32 + mt * 16 + rq;
            float2 v0 = make_float2(acc[mt][nt][0] + b2.x, acc[mt][nt][1] + b2.y);
            float2 v1 = make_float2(acc[mt][nt][2] + b2.x, acc[mt][nt][3] + b2.y);
            *(float2*)&wf[(size_t)r * Cn + col] = v0;
            *(float2*)&wf[(size_t)(r + 8) * Cn + col] = v1;
        }
    }
}

// ---------------------------------------------------------------------------
// Per-row softmax + ArcFace loss, 2 passes (logits bounded -> no max needed).
// ---------------------------------------------------------------------------
__device__ __forceinline__ float block_sum(float v, float* red, int t) {
    red[t] = v; __syncthreads();
#pragma unroll
    for (int s = 128; s; s >>= 1) {
        if (t < s) red[t] += red[t + s];
        __syncthreads();
    }
    float r = red[0]; __syncthreads();
    return r;
}

__global__ __launch_bounds__(256) void rowstats(float* __restrict__ wf,
                                                const int* __restrict__ labels) {
    int row = blockIdx.x;
    float* ptr = wf + (size_t)row * Cn;
    const float4* p4 = (const float4*)ptr;
    float4* pw = (float4*)ptr;
    int label = labels[row];
    int t = threadIdx.x;
    __shared__ float red[256];
    __shared__ float sh_inv;

    float sp = 0.f, sl = 0.f;
    for (int i = t; i < Cn / 4; i += 256) {
        float4 v = p4[i];
        sp += __expf(v.x) + __expf(v.y) + __expf(v.z) + __expf(v.w);
        float e0 = __expf(Sf * v.x), e1 = __expf(Sf * v.y);
        float e2 = __expf(Sf * v.z), e3 = __expf(Sf * v.w);
        int base = i * 4;
        if ((unsigned)(label - base) < 4u) {
            int off = label - base;
            if (off == 0) e0 = 0.f; else if (off == 1) e1 = 0.f;
            else if (off == 2) e2 = 0.f; else e3 = 0.f;
        }
        sl += e0 + e1 + e2 + e3;
    }
    float spr = block_sum(sp, red, t);
    float slr = block_sum(sl, red, t);

    if (t == 0) {
        float wl = ptr[label];
        float cc = fminf(fmaxf(wl, -1.0f + EPSf), 1.0f - EPSf);
        float cosm = cc * COS_M - sqrtf(fmaxf(1.0f - cc * cc, 0.0f)) * SIN_M;
        float total = slr + __expf(Sf * cosm);
        g_loss[row] = logf(total) - Sf * cosm;
        sh_inv = 1.0f / spr;
    }
    __syncthreads();
    float inv = sh_inv;

    for (int i = t; i < Cn / 4; i += 256) {
        float4 v = p4[i];
        v.x = __expf(v.x) * inv;
        v.y = __expf(v.y) * inv;
        v.z = __expf(v.z) * inv;
        v.w = __expf(v.w) * inv;
        pw[i] = v;
    }
}

// ---------------------------------------------------------------------------
__global__ __launch_bounds__(256) void loss_reduce(float* __restrict__ out) {
    __shared__ float red[256];
    int t = threadIdx.x;
    float s = 0.f;
    for (int i = t; i < Bn; i += 256) s += g_loss[i];
    red[t] = s; __syncthreads();
#pragma unroll
    for (int st = 128; st; st >>= 1) {
        if (t < st) red[t] += red[t + st];
        __syncthreads();
    }
    if (t == 0) out[(size_t)Bn * Cn] = red[0] / (float)Bn;
}

// ---------------------------------------------------------------------------
extern "C" void kernel_launch(void* const* d_in, const int* in_sizes, int n_in,
                              void* d_out, int out_size) {
    const float* x      = (const float*)d_in[0];
    const float* W      = (const float*)d_in[1];
    const float* bias   = (const float*)d_in[2];
    const int*   labels = (const int*)d_in[3];
    float* out = (float*)d_out;

    cudaFuncSetAttribute(gemm_mma, cudaFuncAttributeMaxDynamicSharedMemorySize,
                         SM_TOTAL);

    norm_split<<<Bn / 8, 256>>>(x, Bn, Bn, 0);
    norm_split<<<CPAD / 8, 256>>>(W, Cn, CPAD, 1);

    dim3 gg(NRT, NCT);   // row tile fastest -> each B tile loaded once
    gemm_mma<<<gg, 256, SM_TOTAL>>>(bias, out);

    rowstats<<<Bn, 256>>>(out, labels);
    loss_reduce<<<1, 256>>>(out);
}

// round 6
// speedup vs baseline: 2.2599x; 1.0235x over previous
#include <cuda_runtime.h>
#include <cuda_bf16.h>
#include <math.h>
#include <stdint.h>

// Problem constants
#define Bn 2048
#define Cn 50000
#define Dn 128
#define CPAD 50048            // Cn padded to multiple of 64
#define NCT (CPAD / 64)       // 782 column tiles
#define NRT (Bn / 128)        // 16 row tiles
#define Sf 20.0f
#define EPSf 1e-7f
#define COS_M 0.9950041652780258f
#define SIN_M 0.09983341664682815f

// Plain row-major bf16 scratch: [row][128]
__device__ __align__(16) __nv_bfloat16 g_Ah[(size_t)Bn * Dn];
__device__ __align__(16) __nv_bfloat16 g_Al[(size_t)Bn * Dn];
__device__ __align__(16) __nv_bfloat16 g_Bh[(size_t)CPAD * Dn];
__device__ __align__(16) __nv_bfloat16 g_Bl[(size_t)CPAD * Dn];
// Per-(row, coltile) partial sums (written unconditionally -> no zeroing)
__device__ float g_psp[(size_t)Bn * NCT];   // sum exp(wf)
__device__ float g_psl[(size_t)Bn * NCT];   // sum exp(20*wf)
__device__ float g_inv[Bn];
__device__ float g_loss[Bn];

// ---------------------------------------------------------------------------
__device__ __forceinline__ void mma16816(float* c, const uint32_t* a,
                                         uint32_t b0, uint32_t b1) {
    asm volatile(
        "mma.sync.aligned.m16n8k16.row.col.f32.bf16.bf16.f32 "
        "{%0,%1,%2,%3}, {%4,%5,%6,%7}, {%8,%9}, {%0,%1,%2,%3};"
        : "+f"(c[0]), "+f"(c[1]), "+f"(c[2]), "+f"(c[3])
        : "r"(a[0]), "r"(a[1]), "r"(a[2]), "r"(a[3]), "r"(b0), "r"(b1));
}

// ---------------------------------------------------------------------------
// Normalize + split fp32 -> bf16 hi/lo, plain row-major. One warp per row.
// Output arrays bound INSIDE device code (device symbols are invalid as
// host-side kernel args).
// ---------------------------------------------------------------------------
__global__ __launch_bounds__(256) void norm_split(const float* __restrict__ in,
                                                  int nrows, int npad,
                                                  int which) {
    int warp = (blockIdx.x * blockDim.x + threadIdx.x) >> 5;
    int lane = threadIdx.x & 31;
    if (warp >= npad) return;
    float4 v = make_float4(0.f, 0.f, 0.f, 0.f);
    if (warp < nrows) v = ((const float4*)(in + (size_t)warp * Dn))[lane];
    float ss = v.x * v.x + v.y * v.y + v.z * v.z + v.w * v.w;
#pragma unroll
    for (int o = 16; o; o >>= 1) ss += __shfl_xor_sync(0xffffffffu, ss, o);
    float sc = 1.0f / fmaxf(sqrtf(ss), 1e-12f);
    if (warp >= nrows) sc = 0.0f;
    v.x *= sc; v.y *= sc; v.z *= sc; v.w *= sc;

    __nv_bfloat162 h01 = __floats2bfloat162_rn(v.x, v.y);
    __nv_bfloat162 h23 = __floats2bfloat162_rn(v.z, v.w);
    __nv_bfloat162 l01 = __floats2bfloat162_rn(v.x - __bfloat162float(h01.x),
                                               v.y - __bfloat162float(h01.y));
    __nv_bfloat162 l23 = __floats2bfloat162_rn(v.z - __bfloat162float(h23.x),
                                               v.w - __bfloat162float(h23.y));

    __nv_bfloat16* hi = which ? g_Bh : g_Ah;
    __nv_bfloat16* lo = which ? g_Bl : g_Al;
    size_t idx = (size_t)warp * Dn + 4 * lane;
    uint2 hv, lv;
    hv.x = *(uint32_t*)&h01; hv.y = *(uint32_t*)&h23;
    lv.x = *(uint32_t*)&l01; lv.y = *(uint32_t*)&l23;
    *(uint2*)(hi + idx) = hv;
    *(uint2*)(lo + idx) = lv;
}

// ---------------------------------------------------------------------------
// mma.sync bf16 GEMM with fused exp-sum epilogue.
// CTA tile 128x64, 256 threads (8 warps of 32x32), full K=128 in SMEM.
// SMEM as uint32 words, row stride 68 (64 data + 4 pad): 104448 bytes.
// ---------------------------------------------------------------------------
#define RW 68
#define WO_AH 0
#define WO_AL (128 * RW)
#define WO_BH (2 * 128 * RW)
#define WO_BL (2 * 128 * RW + 64 * RW)
#define SM_WORDS (2 * 128 * RW + 2 * 64 * RW)
#define SM_TOTAL (SM_WORDS * 4)

__global__ __launch_bounds__(256, 2) void gemm_mma(const float* __restrict__ bias,
                                                   float* __restrict__ wf) {
    extern __shared__ uint32_t sw[];
    int t = threadIdx.x;
    int w = t >> 5, lane = t & 31;
    int row0 = blockIdx.x * 128;       // row tile fastest: B tile reused 16x
    int col0 = blockIdx.y * 64;
    int ct = blockIdx.y;

    // ---- copies: global row (16 uint4) -> smem row (17 uint4, last = pad) ----
    {
        uint4* s4 = (uint4*)sw;
        const uint4* gah = (const uint4*)(g_Ah + (size_t)row0 * Dn);
        const uint4* gal = (const uint4*)(g_Al + (size_t)row0 * Dn);
#pragma unroll
        for (int i = 0; i < 8; i++) {
            int idx = t + i * 256;
            int r = idx >> 4, q = idx & 15;
            s4[(WO_AH / 4) + r * 17 + q] = gah[r * 16 + q];
            s4[(WO_AL / 4) + r * 17 + q] = gal[r * 16 + q];
        }
        const uint4* gbh = (const uint4*)(g_Bh + (size_t)col0 * Dn);
        const uint4* gbl = (const uint4*)(g_Bl + (size_t)col0 * Dn);
#pragma unroll
        for (int i = 0; i < 4; i++) {
            int idx = t + i * 256;
            int r = idx >> 4, q = idx & 15;
            s4[(WO_BH / 4) + r * 17 + q] = gbh[r * 16 + q];
            s4[(WO_BL / 4) + r * 17 + q] = gbl[r * 16 + q];
        }
    }
    __syncthreads();

    int wr = w & 3;                    // row group: 4 x 32 rows
    int wc = w >> 2;                   // col group: 2 x 32 cols
    int rq = lane >> 2;                // groupID
    int tig = lane & 3;                // threadID_in_group

    float acc[2][4][4];
#pragma unroll
    for (int mt = 0; mt < 2; mt++)
#pragma unroll
        for (int nt = 0; nt < 4; nt++)
#pragma unroll
            for (int i = 0; i < 4; i++) acc[mt][nt][i] = 0.f;

#pragma unroll
    for (int ks = 0; ks < 8; ks++) {
        int kw = ks * 8;
        uint32_t ah[2][4], al[2][4];
#pragma unroll
        for (int mt = 0; mt < 2; mt++) {
            int r0 = (wr * 32 + mt * 16 + rq) * RW + kw + tig;
            int r1 = r0 + 8 * RW;
            ah[mt][0] = sw[WO_AH + r0];
            ah[mt][1] = sw[WO_AH + r1];
            ah[mt][2] = sw[WO_AH + r0 + 4];
            ah[mt][3] = sw[WO_AH + r1 + 4];
            al[mt][0] = sw[WO_AL + r0];
            al[mt][1] = sw[WO_AL + r1];
            al[mt][2] = sw[WO_AL + r0 + 4];
            al[mt][3] = sw[WO_AL + r1 + 4];
        }
#pragma unroll
        for (int nt = 0; nt < 4; nt++) {
            int rb = (wc * 32 + nt * 8 + rq) * RW + kw + tig;
            uint32_t bh0 = sw[WO_BH + rb];
            uint32_t bh1 = sw[WO_BH + rb + 4];
            uint32_t bl0 = sw[WO_BL + rb];
            uint32_t bl1 = sw[WO_BL + rb + 4];
#pragma unroll
            for (int mt = 0; mt < 2; mt++) {
                mma16816(acc[mt][nt], ah[mt], bh0, bh1);  // Ah*Bh
                mma16816(acc[mt][nt], ah[mt], bl0, bl1);  // Ah*Bl
                mma16816(acc[mt][nt], al[mt], bh0, bh1);  // Al*Bh
            }
        }
    }
    __syncthreads();   // tiles dead; smem reused for row-sum combine

    // ---- epilogue: bias + store + per-row exp sums ----
    float rsp[4] = {0.f, 0.f, 0.f, 0.f};   // rows mt*16+rq, mt*16+8+rq
    float rsl[4] = {0.f, 0.f, 0.f, 0.f};
    int cq = tig * 2;
#pragma unroll
    for (int nt = 0; nt < 4; nt++) {
        int col = col0 + wc * 32 + nt * 8 + cq;
        if (col >= Cn) continue;
        float2 b2 = *(const float2*)&bias[col];
#pragma unroll
        for (int mt = 0; mt < 2; mt++) {
            int r = row0 + wr * 32 + mt * 16 + rq;
            float v00 = acc[mt][nt][0] + b2.x, v01 = acc[mt][nt][1] + b2.y;
            float v10 = acc[mt][nt][2] + b2.x, v11 = acc[mt][nt][3] + b2.y;
            *(float2*)&wf[(size_t)r * Cn + col] = make_float2(v00, v01);
            *(float2*)&wf[(size_t)(r + 8) * Cn + col] = make_float2(v10, v11);
            rsp[2 * mt]     += __expf(v00) + __expf(v01);
            rsp[2 * mt + 1] += __expf(v10) + __expf(v11);
            rsl[2 * mt]     += __expf(Sf * v00) + __expf(Sf * v01);
            rsl[2 * mt + 1] += __expf(Sf * v10) + __expf(Sf * v11);
        }
    }
    // reduce over the 4 lanes of each row group (tig bits 0..1)
#pragma unroll
    for (int j = 0; j < 4; j++) {
        rsp[j] += __shfl_xor_sync(0xffffffffu, rsp[j], 1);
        rsp[j] += __shfl_xor_sync(0xffffffffu, rsp[j], 2);
        rsl[j] += __shfl_xor_sync(0xffffffffu, rsl[j], 1);
        rsl[j] += __shfl_xor_sync(0xffffffffu, rsl[j], 2);
    }
    float* ssp = (float*)sw;           // [2][128]
    float* ssl = ((float*)sw) + 256;   // [2][128]
    if (tig == 0) {
#pragma unroll
        for (int j = 0; j < 4; j++) {
            int lrow = wr * 32 + (j >> 1) * 16 + (j & 1) * 8 + rq;
            ssp[wc * 128 + lrow] = rsp[j];
            ssl[wc * 128 + lrow] = rsl[j];
        }
    }
    __syncthreads();
    if (t < 128) {
        g_psp[(size_t)(row0 + t) * NCT + ct] = ssp[t] + ssp[128 + t];
        g_psl[(size_t)(row0 + t) * NCT + ct] = ssl[t] + ssl[128 + t];
    }
}

// ---------------------------------------------------------------------------
// Per-row: sum partials, fix label term, compute inv + loss. Block per row.
// ---------------------------------------------------------------------------
__global__ __launch_bounds__(256) void row_final(const float* __restrict__ wf,
                                                 const int* __restrict__ labels) {
    int row = blockIdx.x;
    int t = threadIdx.x;
    __shared__ float red[512];
    float sp = 0.f, sl = 0.f;
    const float* pp = g_psp + (size_t)row * NCT;
    const float* pl = g_psl + (size_t)row * NCT;
    for (int i = t; i < NCT; i += 256) { sp += pp[i]; sl += pl[i]; }
    red[t] = sp; red[256 + t] = sl;
    __syncthreads();
#pragma unroll
    for (int s = 128; s; s >>= 1) {
        if (t < s) { red[t] += red[t + s]; red[256 + t] += red[256 + t + s]; }
        __syncthreads();
    }
    if (t == 0) {
        float spr = red[0], slr = red[256];
        float wl = wf[(size_t)row * Cn + labels[row]];
        float cc = fminf(fmaxf(wl, -1.0f + EPSf), 1.0f - EPSf);
        float cosm = cc * COS_M - sqrtf(fmaxf(1.0f - cc * cc, 0.0f)) * SIN_M;
        float total = slr - __expf(Sf * wl) + __expf(Sf * cosm);
        g_loss[row] = logf(total) - Sf * cosm;
        g_inv[row] = 1.0f / spr;
    }
}

// ---------------------------------------------------------------------------
// Elementwise: pred = exp(wf) * inv[row].  grid (Cn/4 per row, Bn rows).
// ---------------------------------------------------------------------------
__global__ __launch_bounds__(256) void finalize(float* __restrict__ wf) {
    int row = blockIdx.y;
    int i = blockIdx.x * 256 + threadIdx.x;         // float4 index in row
    if (i >= Cn / 4) return;
    float inv = g_inv[row];
    float4* p = (float4*)(wf + (size_t)row * Cn) + i;
    float4 v = *p;
    v.x = __expf(v.x) * inv;
    v.y = __expf(v.y) * inv;
    v.z = __expf(v.z) * inv;
    v.w = __expf(v.w) * inv;
    *p = v;
}

// ---------------------------------------------------------------------------
__global__ __launch_bounds__(256) void loss_reduce(float* __restrict__ out) {
    __shared__ float red[256];
    int t = threadIdx.x;
    float s = 0.f;
    for (int i = t; i < Bn; i += 256) s += g_loss[i];
    red[t] = s; __syncthreads();
#pragma unroll
    for (int st = 128; st; st >>= 1) {
        if (t < st) red[t] += red[t + st];
        __syncthreads();
    }
    if (t == 0) out[(size_t)Bn * Cn] = red[0] / (float)Bn;
}

// ---------------------------------------------------------------------------
extern "C" void kernel_launch(void* const* d_in, const int* in_sizes, int n_in,
                              void* d_out, int out_size) {
    const float* x      = (const float*)d_in[0];
    const float* W      = (const float*)d_in[1];
    const float* bias   = (const float*)d_in[2];
    const int*   labels = (const int*)d_in[3];
    float* out = (float*)d_out;

    cudaFuncSetAttribute(gemm_mma, cudaFuncAttributeMaxDynamicSharedMemorySize,
                         SM_TOTAL);

    norm_split<<<Bn / 8, 256>>>(x, Bn, Bn, 0);
    norm_split<<<CPAD / 8, 256>>>(W, Cn, CPAD, 1);

    dim3 gg(NRT, NCT);   // row tile fastest -> each B tile loaded once
    gemm_mma<<<gg, 256, SM_TOTAL>>>(bias, out);

    row_final<<<Bn, 256>>>(out, labels);

    dim3 gf((Cn / 4 + 255) / 256, Bn);
    finalize<<<gf, 256>>>(out);

    loss_reduce<<<1, 256>>>(out);
}